// round 14
// baseline (speedup 1.0000x reference)
#include <cuda_runtime.h>
#include <cuda_bf16.h>
#include <cstdint>

#define DINLINE __device__ __forceinline__

#define VN    8192
#define F0N   16
#define BATCH 32
#define NCH   512
#define KDEG  8

// ---------------- persistent device scratch ----------------
__device__ float          g_a[KDEG + 1];
__device__ __nv_bfloat16  g_Lbf[(size_t)VN * VN];
__device__ __nv_bfloat16  g_W0[(size_t)NCH * VN];
__device__ __nv_bfloat16  g_W1[(size_t)NCH * VN];
__device__ float          g_out[(size_t)NCH * VN];
__device__ float          g_xg[(size_t)BATCH * 32768];
__device__ float          g_xhid_pre[512 * 32];   // [f][b]
__device__ float          g_h1pre[256 * 32];      // [f][b]
__device__ float          g_h1n[256 * 32];        // [k][b]
__device__ float          g_h2n[128 * 32];        // [o][b]

// ---------------- PTX helpers (base-target safe: no tcgen05) ----------------
DINLINE uint32_t smem_u32(const void* p) {
    uint32_t a;
    asm("{ .reg .u64 t; cvta.to.shared.u64 t, %1; cvt.u32.u64 %0, t; }" : "=r"(a) : "l"(p));
    return a;
}
DINLINE void cpasync16(uint32_t dst, const void* src) {
    asm volatile("cp.async.cg.shared.global [%0], [%1], 16;" :: "r"(dst), "l"(src) : "memory");
}
DINLINE void cp_commit() { asm volatile("cp.async.commit_group;" ::: "memory"); }
DINLINE void cp_wait1()  { asm volatile("cp.async.wait_group 1;" ::: "memory"); }

DINLINE void ldsm_x4(uint32_t& r0, uint32_t& r1, uint32_t& r2, uint32_t& r3, uint32_t addr) {
    asm volatile("ldmatrix.sync.aligned.m8n8.x4.shared.b16 {%0,%1,%2,%3}, [%4];"
                 : "=r"(r0), "=r"(r1), "=r"(r2), "=r"(r3) : "r"(addr));
}
DINLINE void mma16816(float* c, const uint32_t* a, const uint32_t* b) {
    asm volatile(
        "mma.sync.aligned.m16n8k16.row.col.f32.bf16.bf16.f32 "
        "{%0,%1,%2,%3}, {%4,%5,%6,%7}, {%8,%9}, {%0,%1,%2,%3};"
        : "+f"(c[0]), "+f"(c[1]), "+f"(c[2]), "+f"(c[3])
        : "r"(a[0]), "r"(a[1]), "r"(a[2]), "r"(a[3]), "r"(b[0]), "r"(b[1]));
}

// ---------------- Bernstein coefficients ----------------
__global__ void k_bern(const float* __restrict__ theta) {
    int j = threadIdx.x;
    if (j <= KDEG) {
        float acc = 0.f;
        for (int k = 0; k <= j; k++) {
            int n = KDEG - k, r = j - k;
            float c = 1.f;
            for (int i = 0; i < r; i++) c = c * (float)(n - i) / (float)(i + 1);
            float sgn = ((j - k) & 1) ? -1.f : 1.f;
            acc += theta[k] * c * sgn;
        }
        g_a[j] = acc * (float)(1 << (KDEG - j));
    }
}

// ---------------- L fp32 -> bf16 ----------------
__global__ void k_cvtL(const float* __restrict__ L) {
    size_t i = ((size_t)blockIdx.x * 256 + threadIdx.x) * 4;
    float4 v = *(const float4*)(L + i);
    __nv_bfloat162* o = (__nv_bfloat162*)(g_Lbf + i);
    o[0] = __floats2bfloat162_rn(v.x, v.y);
    o[1] = __floats2bfloat162_rn(v.z, v.w);
}

// ---------------- transpose x -> W0 (bf16), out = a0*x ----------------
__global__ void k_init(const float* __restrict__ x) {
    __shared__ float s[64 * 17];
    int b = blockIdx.y, vb = blockIdx.x * 64, tid = threadIdx.x;
    for (int idx = tid; idx < 1024; idx += 256) {
        int vl = idx >> 4, f = idx & 15;
        s[vl * 17 + f] = x[(size_t)(b * VN + vb + vl) * F0N + f];
    }
    __syncthreads();
    float a0 = g_a[0];
    for (int idx = tid; idx < 1024; idx += 256) {
        int f = idx >> 6, vl = idx & 63;
        float v = s[vl * 17 + f];
        size_t o = (size_t)(b * F0N + f) * VN + vb + vl;
        g_W0[o]  = __float2bfloat16(v);
        g_out[o] = a0 * v;
    }
}

// ---------------- chain GEMM: D(512x8192) = W @ L^T  (mma.sync bf16) ----------------
// CTA tile 128x128x64, 256 threads (8 warps: 2m x 4n), warp tile 64x32.
// 3-stage cp.async circular pipeline (wait_group 1 -> issued 2 stages ahead),
// 4 mma substeps per stage -> 128 barriers total (half of R11).
#define BKC   64
#define NTK   (VN / BKC)       // 128 k-stages
#define ROWB  144              // bytes per 64-elem k-row (128 data + 16 pad; 144/16=9 odd -> conflict-free)
#define TILEB (128 * ROWB)     // 18432 B per tile per stage
#define SSTG  3
#define GEMM_SMEM (2 * SSTG * TILEB)   // A[3] + B[3] = 110592 B

__global__ void __launch_bounds__(256, 2) k_gemm(int srcW0, int jidx) {
    extern __shared__ __align__(16) char smem[];

    const __nv_bfloat16* __restrict__ A  = srcW0 ? g_W0 : g_W1;
    __nv_bfloat16* __restrict__       Wn = srcW0 ? g_W1 : g_W0;

    int tid = threadIdx.x, lane = tid & 31, wid = tid >> 5;
    int wm = wid >> 2, wn = wid & 3;
    int m0 = blockIdx.x * 128, n0 = blockIdx.y * 128;

    uint32_t aS = smem_u32(smem);            // A stages: aS + slot*TILEB
    uint32_t bS = aS + SSTG * TILEB;         // B stages: bS + slot*TILEB

    // cp.async mapping: row = tid>>1 (0..127), half = (tid&1)*64 bytes; 4 chunks each.
    int r0 = tid >> 1, c0 = (tid & 1) * 64;
    const char* gA0 = (const char*)(A + (size_t)(m0 + r0) * VN) + c0;
    const char* gB0 = (const char*)(g_Lbf + (size_t)(n0 + r0) * VN) + c0;
    uint32_t dA0 = aS + r0 * ROWB + c0;
    uint32_t dB0 = bS + r0 * ROWB + c0;

    // A ldmatrix lane addresses: 4 fragments of 16x16 (k-substep adds s*32)
    uint32_t aAddr[4];
#pragma unroll
    for (int mi = 0; mi < 4; mi++)
        aAddr[mi] = aS + (uint32_t)(wm * 64 + mi * 16 + (lane & 15)) * ROWB + (lane >> 4) * 16;
    // B merged ldmatrix: one x4 covers ni=2p,2p+1 (both k-halves)
    uint32_t bAddr[2];
#pragma unroll
    for (int p = 0; p < 2; p++)
        bAddr[p] = bS + (uint32_t)(wn * 32 + p * 16 + (lane >> 4) * 8 + (lane & 7)) * ROWB
                      + ((lane >> 3) & 1) * 16;

    float acc[4][4][4];
#pragma unroll
    for (int mi = 0; mi < 4; mi++)
#pragma unroll
        for (int ni = 0; ni < 4; ni++)
#pragma unroll
            for (int q = 0; q < 4; q++) acc[mi][ni][q] = 0.f;

    // prologue: issue stages 0..1
#pragma unroll
    for (int s = 0; s < SSTG - 1; s++) {
        uint32_t so = (uint32_t)s * TILEB;
        size_t go = (size_t)s * (BKC * 2);
#pragma unroll
        for (int c = 0; c < 4; c++) {
            cpasync16(dA0 + so + c * 16, gA0 + go + c * 16);
            cpasync16(dB0 + so + c * 16, gB0 + go + c * 16);
        }
        cp_commit();
    }

    int slot = 0, pslot = SSTG - 1;
    for (int kt = 0; kt < NTK; kt++) {
        cp_wait1();          // stage kt landed (issued 2 stages ago)
        __syncthreads();     // all warps done reading the slot being refilled
        if (kt + SSTG - 1 < NTK) {
            uint32_t so = (uint32_t)pslot * TILEB;
            size_t go = (size_t)(kt + SSTG - 1) * (BKC * 2);
#pragma unroll
            for (int c = 0; c < 4; c++) {
                cpasync16(dA0 + so + c * 16, gA0 + go + c * 16);
                cpasync16(dB0 + so + c * 16, gB0 + go + c * 16);
            }
            cp_commit();
        }
        uint32_t boff = (uint32_t)slot * TILEB;
#pragma unroll
        for (int s = 0; s < 4; s++) {
            uint32_t a[4][4], b[4][2];
#pragma unroll
            for (int mi = 0; mi < 4; mi++)
                ldsm_x4(a[mi][0], a[mi][1], a[mi][2], a[mi][3], aAddr[mi] + boff + s * 32);
#pragma unroll
            for (int p = 0; p < 2; p++)
                ldsm_x4(b[2 * p][0], b[2 * p][1], b[2 * p + 1][0], b[2 * p + 1][1],
                        bAddr[p] + boff + s * 32);
#pragma unroll
            for (int mi = 0; mi < 4; mi++)
#pragma unroll
                for (int ni = 0; ni < 4; ni++)
                    mma16816(acc[mi][ni], a[mi], b[ni]);
        }
        slot = (slot + 1 == SSTG) ? 0 : slot + 1;
        pslot = (pslot + 1 == SSTG) ? 0 : pslot + 1;
    }

    // epilogue: g_out += a_j * D ; Wn = bf16(D)
    float aj = g_a[jidx];
#pragma unroll
    for (int mi = 0; mi < 4; mi++) {
#pragma unroll
        for (int ni = 0; ni < 4; ni++) {
            int mA = m0 + wm * 64 + mi * 16 + (lane >> 2);
            int nA = n0 + wn * 32 + ni * 8 + (lane & 3) * 2;
#pragma unroll
            for (int hf = 0; hf < 2; hf++) {
                int m = mA + hf * 8;
                float v0 = acc[mi][ni][hf * 2 + 0];
                float v1 = acc[mi][ni][hf * 2 + 1];
                float* po = &g_out[(size_t)m * VN + nA];
                float2 o = *(float2*)po;
                o.x += aj * v0; o.y += aj * v1;
                *(float2*)po = o;
                *(__nv_bfloat162*)&Wn[(size_t)m * VN + nA] = __floats2bfloat162_rn(v0, v1);
            }
        }
    }
}

// ---------------- L2 normalize each chain row over V ----------------
__global__ void k_norm() {
    int n = blockIdx.x, tid = threadIdx.x;
    float* row = g_out + (size_t)n * VN;
    float loc[32];
    float ss = 0.f;
#pragma unroll
    for (int i = 0; i < 32; i++) {
        float v = row[i * 256 + tid];
        loc[i] = v;
        ss += v * v;
    }
    __shared__ float red[8];
    for (int o = 16; o; o >>= 1) ss += __shfl_xor_sync(0xffffffffu, ss, o);
    if ((tid & 31) == 0) red[tid >> 5] = ss;
    __syncthreads();
    if (tid == 0) {
        float t = 0.f;
        for (int i = 0; i < 8; i++) t += red[i];
        red[0] = t;
    }
    __syncthreads();
    float inv = 1.f / fmaxf(sqrtf(red[0]), 1e-12f);
#pragma unroll
    for (int i = 0; i < 32; i++) row[i * 256 + tid] = loc[i] * inv;
}

// ---------------- cl1 (16->32) + relu + maxpool8 -> xg ----------------
__global__ void k_cl1pool(const float* __restrict__ w, const float* __restrict__ bias) {
    int vg = blockIdx.x, b = blockIdx.y, c = threadIdx.x;
    float wr[16];
#pragma unroll
    for (int f = 0; f < 16; f++) wr[f] = w[c * 16 + f];
    float bb = bias[c];
    float m = 0.f;
    for (int vv = 0; vv < 8; vv++) {
        int v = vg * 8 + vv;
        float acc = bb;
#pragma unroll
        for (int f = 0; f < 16; f++)
            acc += wr[f] * g_out[(size_t)(b * F0N + f) * VN + v];
        m = fmaxf(m, acc);
    }
    g_xg[(size_t)b * 32768 + vg * 32 + c] = m;
}

__global__ void k_zero() {
    int i = blockIdx.x * 256 + threadIdx.x;
    if (i < 512 * 32) g_xhid_pre[i] = 0.f;
    if (i < 256 * 32) g_h1pre[i] = 0.f;
}

// ---------------- big MLP GEMMs (split-K, atomic accumulate) ----------------
// which==1: X = Xext (x_in, K=131072), acc = g_h1pre  (nn_fc1, F=256)
// which==0: X = g_xg (K=32768),        acc = g_xhid_pre (fc1, F=512)
// NOTE: accumulator selected in DEVICE code — never pass a __device__ symbol
// from host (host shadow address + GB300 ATS silently writes host memory).
__global__ void __launch_bounds__(256) k_mlpgemm(
    const float* __restrict__ Xext, int which,
    const float* __restrict__ W, int K) {
    __shared__ float xs[256 * 33];
    const float* __restrict__ X = which ? Xext : g_xg;
    float* __restrict__ acc = which ? g_h1pre : g_xhid_pre;
    int tid = threadIdx.x, lane = tid & 31, wrp = tid >> 5;
    int Kslice = K / gridDim.y;
    int kbase0 = blockIdx.y * Kslice;
    int f0 = blockIdx.x * 16 + wrp * 2;
    const float* w0p = W + (size_t)f0 * K;
    const float* w1p = W + (size_t)(f0 + 1) * K;
    float a0 = 0.f, a1 = 0.f;

    for (int kc = 0; kc < Kslice; kc += 256) {
        int kb = kbase0 + kc;
#pragma unroll
        for (int i = 0; i < 32; i++)
            xs[tid * 33 + i] = X[(size_t)i * K + kb + tid];
        __syncthreads();
#pragma unroll 8
        for (int kk = 0; kk < 256; kk++) {
            float xv = xs[kk * 33 + lane];
            a0 += w0p[kb + kk] * xv;
            a1 += w1p[kb + kk] * xv;
        }
        __syncthreads();
    }
    atomicAdd(&acc[f0 * 32 + lane], a0);
    atomicAdd(&acc[(f0 + 1) * 32 + lane], a1);
}

// ---------------- bias+relu+BN (train stats) for h1 ----------------
__global__ void k_bn1(const float* __restrict__ bias, const float* __restrict__ gamma,
                      const float* __restrict__ beta) {
    int f = blockIdx.x, b = threadIdx.x;
    float v = fmaxf(g_h1pre[f * 32 + b] + bias[f], 0.f);
    float s = v, s2 = v * v;
    for (int o = 16; o; o >>= 1) {
        s  += __shfl_xor_sync(0xffffffffu, s, o);
        s2 += __shfl_xor_sync(0xffffffffu, s2, o);
    }
    float mean = s / 32.f, var = s2 / 32.f - mean * mean;
    g_h1n[f * 32 + b] = (v - mean) * rsqrtf(var + 1e-5f) * gamma[f] + beta[f];
}

// ---------------- fc2 + relu + BN2 ----------------
__global__ void k_fc2bn2(const float* __restrict__ w, const float* __restrict__ bias,
                         const float* __restrict__ gamma, const float* __restrict__ beta) {
    int o = blockIdx.x, b = threadIdx.x;
    float acc = bias[o];
    for (int k = 0; k < 256; k++)
        acc += w[o * 256 + k] * g_h1n[k * 32 + b];
    float v = fmaxf(acc, 0.f);
    float s = v, s2 = v * v;
    for (int sh = 16; sh; sh >>= 1) {
        s  += __shfl_xor_sync(0xffffffffu, s, sh);
        s2 += __shfl_xor_sync(0xffffffffu, s2, sh);
    }
    float mean = s / 32.f, var = s2 / 32.f - mean * mean;
    g_h2n[o * 32 + b] = (v - mean) * rsqrtf(var + 1e-5f) * gamma[o] + beta[o];
}

// ---------------- fusion head ----------------
__global__ void k_head(const float* __restrict__ fc1b, const float* __restrict__ sw,
                       const float* __restrict__ sb, float* __restrict__ out) {
    int tid = threadIdx.x;
    if (tid >= 320) return;
    int o = tid >> 5, b = tid & 31;
    float acc = sb[o];
    for (int f = 0; f < 512; f++)
        acc += sw[o * 640 + f] * fmaxf(g_xhid_pre[f * 32 + b] + fc1b[f], 0.f);
    for (int f = 0; f < 128; f++)
        acc += sw[o * 640 + 512 + f] * g_h2n[f * 32 + b];
    out[b * 10 + o] = acc;
}

// ---------------- launch ----------------
extern "C" void kernel_launch(void* const* d_in, const int* in_sizes, int n_in,
                              void* d_out, int out_size) {
    const float* x_in     = (const float*)d_in[0];
    const float* L        = (const float*)d_in[1];
    const float* theta    = (const float*)d_in[2];
    const float* cl1_w    = (const float*)d_in[3];
    const float* cl1_b    = (const float*)d_in[4];
    const float* fc1_w    = (const float*)d_in[5];
    const float* fc1_b    = (const float*)d_in[6];
    const float* nn1_w    = (const float*)d_in[7];
    const float* nn1_b    = (const float*)d_in[8];
    const float* bn1_g    = (const float*)d_in[9];
    const float* bn1_b    = (const float*)d_in[10];
    const float* nn2_w    = (const float*)d_in[11];
    const float* nn2_b    = (const float*)d_in[12];
    const float* bn2_g    = (const float*)d_in[13];
    const float* bn2_b    = (const float*)d_in[14];
    const float* sum2_w   = (const float*)d_in[15];
    const float* sum2_b   = (const float*)d_in[16];
    float* out = (float*)d_out;

    static int smem_set = 0;
    if (!smem_set) {
        cudaFuncSetAttribute(k_gemm, cudaFuncAttributeMaxDynamicSharedMemorySize, GEMM_SMEM);
        smem_set = 1;
    }

    k_bern<<<1, 32>>>(theta);
    k_cvtL<<<65536, 256>>>(L);
    k_init<<<dim3(128, 32), 256>>>(x_in);

    for (int j = 1; j <= KDEG; j++)
        k_gemm<<<dim3(4, 64), 256, GEMM_SMEM>>>((j & 1) ? 1 : 0, j);

    k_norm<<<512, 256>>>();
    k_cl1pool<<<dim3(1024, 32), 32>>>(cl1_w, cl1_b);
    k_zero<<<96, 256>>>();
    k_mlpgemm<<<dim3(16, 16), 256>>>(x_in, 1, nn1_w, 131072);
    k_mlpgemm<<<dim3(32, 8), 256>>>(nullptr, 0, fc1_w, 32768);
    k_bn1<<<256, 32>>>(nn1_b, bn1_g, bn1_b);
    k_fc2bn2<<<128, 32>>>(nn2_w, nn2_b, bn2_g, bn2_b);
    k_head<<<1, 320>>>(fc1_b, sum2_w, sum2_b, out);
}

// round 16
// speedup vs baseline: 1.2574x; 1.2574x over previous
#include <cuda_runtime.h>
#include <cuda_bf16.h>
#include <cstdint>

#define DINLINE __device__ __forceinline__

#define VN    8192
#define F0N   16
#define BATCH 32
#define NCH   512
#define KDEG  8

// ---------------- persistent device scratch ----------------
__device__ float          g_a[KDEG + 1];
__device__ __nv_bfloat16  g_Lbf[(size_t)VN * VN];
__device__ __nv_bfloat16  g_W0[(size_t)NCH * VN];
__device__ __nv_bfloat16  g_W1[(size_t)NCH * VN];
__device__ float          g_out[(size_t)NCH * VN];
__device__ float          g_xg[(size_t)BATCH * 32768];
__device__ float          g_xhid_pre[512 * 32];   // [f][b]
__device__ float          g_h1pre[256 * 32];      // [f][b]
__device__ float          g_h1n[256 * 32];        // [k][b]
__device__ float          g_h2n[128 * 32];        // [o][b]

// ---------------- PTX helpers (base-target safe: no tcgen05) ----------------
DINLINE uint32_t smem_u32(const void* p) {
    uint32_t a;
    asm("{ .reg .u64 t; cvta.to.shared.u64 t, %1; cvt.u32.u64 %0, t; }" : "=r"(a) : "l"(p));
    return a;
}
DINLINE void cpasync16(uint32_t dst, const void* src) {
    asm volatile("cp.async.cg.shared.global [%0], [%1], 16;" :: "r"(dst), "l"(src) : "memory");
}
DINLINE void cp_commit() { asm volatile("cp.async.commit_group;" ::: "memory"); }
DINLINE void cp_wait2()  { asm volatile("cp.async.wait_group 2;" ::: "memory"); }

DINLINE void ldsm_x4(uint32_t& r0, uint32_t& r1, uint32_t& r2, uint32_t& r3, uint32_t addr) {
    asm volatile("ldmatrix.sync.aligned.m8n8.x4.shared.b16 {%0,%1,%2,%3}, [%4];"
                 : "=r"(r0), "=r"(r1), "=r"(r2), "=r"(r3) : "r"(addr));
}
DINLINE void mma16816(float* c, const uint32_t* a, const uint32_t* b) {
    asm volatile(
        "mma.sync.aligned.m16n8k16.row.col.f32.bf16.bf16.f32 "
        "{%0,%1,%2,%3}, {%4,%5,%6,%7}, {%8,%9}, {%0,%1,%2,%3};"
        : "+f"(c[0]), "+f"(c[1]), "+f"(c[2]), "+f"(c[3])
        : "r"(a[0]), "r"(a[1]), "r"(a[2]), "r"(a[3]), "r"(b[0]), "r"(b[1]));
}

// ---------------- Bernstein coefficients ----------------
__global__ void k_bern(const float* __restrict__ theta) {
    int j = threadIdx.x;
    if (j <= KDEG) {
        float acc = 0.f;
        for (int k = 0; k <= j; k++) {
            int n = KDEG - k, r = j - k;
            float c = 1.f;
            for (int i = 0; i < r; i++) c = c * (float)(n - i) / (float)(i + 1);
            float sgn = ((j - k) & 1) ? -1.f : 1.f;
            acc += theta[k] * c * sgn;
        }
        g_a[j] = acc * (float)(1 << (KDEG - j));
    }
}

// ---------------- L fp32 -> bf16 ----------------
__global__ void k_cvtL(const float* __restrict__ L) {
    size_t i = ((size_t)blockIdx.x * 256 + threadIdx.x) * 4;
    float4 v = *(const float4*)(L + i);
    __nv_bfloat162* o = (__nv_bfloat162*)(g_Lbf + i);
    o[0] = __floats2bfloat162_rn(v.x, v.y);
    o[1] = __floats2bfloat162_rn(v.z, v.w);
}

// ---------------- transpose x -> W0 (bf16), out = a0*x ----------------
__global__ void k_init(const float* __restrict__ x) {
    __shared__ float s[64 * 17];
    int b = blockIdx.y, vb = blockIdx.x * 64, tid = threadIdx.x;
    for (int idx = tid; idx < 1024; idx += 256) {
        int vl = idx >> 4, f = idx & 15;
        s[vl * 17 + f] = x[(size_t)(b * VN + vb + vl) * F0N + f];
    }
    __syncthreads();
    float a0 = g_a[0];
    for (int idx = tid; idx < 1024; idx += 256) {
        int f = idx >> 6, vl = idx & 63;
        float v = s[vl * 17 + f];
        size_t o = (size_t)(b * F0N + f) * VN + vb + vl;
        g_W0[o]  = __float2bfloat16(v);
        g_out[o] = a0 * v;
    }
}

// ---------------- chain GEMM: D(512x8192) = W @ L^T  (mma.sync bf16) ----------------
// CTA tile 128x128x32, 256 threads (8 warps: 2m x 4n), warp tile 64x32.
// 4-stage cp.async circular pipeline (wait_group 2 -> data requested 3 stages ahead).
// EXACT R11 geometry (best measured: 240us/launch).
#define BKC   32
#define NTK   (VN / BKC)       // 256 k-stages
#define ROWB  80               // bytes per 32-elem k-row in smem (64 data + 16 pad)
#define TILEB (128 * ROWB)     // 10240 B per tile per stage
#define SSTG  4
#define GEMM_SMEM (2 * SSTG * TILEB)   // A[4] + B[4] = 81920 B

__global__ void __launch_bounds__(256, 2) k_gemm(int srcW0, int jidx) {
    extern __shared__ __align__(16) char smem[];

    const __nv_bfloat16* __restrict__ A  = srcW0 ? g_W0 : g_W1;
    __nv_bfloat16* __restrict__       Wn = srcW0 ? g_W1 : g_W0;

    int tid = threadIdx.x, lane = tid & 31, wid = tid >> 5;
    int wm = wid >> 2, wn = wid & 3;
    int m0 = blockIdx.x * 128, n0 = blockIdx.y * 128;

    uint32_t aS = smem_u32(smem);            // A stages: aS + s*TILEB
    uint32_t bS = aS + SSTG * TILEB;         // B stages: bS + s*TILEB

    // cp.async mapping: rows r0 and r0+64, one 16B chunk each (per A and B)
    int r0 = tid >> 2, c0 = tid & 3;
    int r1 = r0 + 64;
    const char* gA0 = (const char*)(A + (size_t)(m0 + r0) * VN) + c0 * 16;
    const char* gA1 = (const char*)(A + (size_t)(m0 + r1) * VN) + c0 * 16;
    const char* gB0 = (const char*)(g_Lbf + (size_t)(n0 + r0) * VN) + c0 * 16;
    const char* gB1 = (const char*)(g_Lbf + (size_t)(n0 + r1) * VN) + c0 * 16;
    uint32_t dA0 = aS + r0 * ROWB + c0 * 16, dA1 = aS + r1 * ROWB + c0 * 16;
    uint32_t dB0 = bS + r0 * ROWB + c0 * 16, dB1 = bS + r1 * ROWB + c0 * 16;

    // A ldmatrix lane addresses: 4 fragments of 16x16
    uint32_t aAddr[4];
#pragma unroll
    for (int mi = 0; mi < 4; mi++)
        aAddr[mi] = aS + (uint32_t)(wm * 64 + mi * 16 + (lane & 15)) * ROWB + (lane >> 4) * 16;
    // B merged ldmatrix: one x4 covers ni=2p,2p+1 (both k-halves).
    uint32_t bAddr[2];
#pragma unroll
    for (int p = 0; p < 2; p++)
        bAddr[p] = bS + (uint32_t)(wn * 32 + p * 16 + (lane >> 4) * 8 + (lane & 7)) * ROWB
                      + ((lane >> 3) & 1) * 16;

    float acc[4][4][4];
#pragma unroll
    for (int mi = 0; mi < 4; mi++)
#pragma unroll
        for (int ni = 0; ni < 4; ni++)
#pragma unroll
            for (int q = 0; q < 4; q++) acc[mi][ni][q] = 0.f;

    // prologue: issue stages 0..2
#pragma unroll
    for (int s = 0; s < SSTG - 1; s++) {
        uint32_t so = (uint32_t)s * TILEB;
        size_t go = (size_t)s * (BKC * 2);
        cpasync16(dA0 + so, gA0 + go); cpasync16(dA1 + so, gA1 + go);
        cpasync16(dB0 + so, gB0 + go); cpasync16(dB1 + so, gB1 + go);
        cp_commit();
    }

    for (int kt = 0; kt < NTK; kt++) {
        cp_wait2();          // stage kt landed (requested 3 stages ago)
        __syncthreads();     // all warps done reading the slot being refilled
        if (kt + SSTG - 1 < NTK) {
            uint32_t so = (uint32_t)((kt + SSTG - 1) & (SSTG - 1)) * TILEB;
            size_t go = (size_t)(kt + SSTG - 1) * (BKC * 2);
            cpasync16(dA0 + so, gA0 + go); cpasync16(dA1 + so, gA1 + go);
            cpasync16(dB0 + so, gB0 + go); cpasync16(dB1 + so, gB1 + go);
            cp_commit();
        }
        uint32_t boff = (uint32_t)(kt & (SSTG - 1)) * TILEB;
#pragma unroll
        for (int s = 0; s < 2; s++) {
            uint32_t a[4][4], b[4][2];
#pragma unroll
            for (int mi = 0; mi < 4; mi++)
                ldsm_x4(a[mi][0], a[mi][1], a[mi][2], a[mi][3], aAddr[mi] + boff + s * 32);
#pragma unroll
            for (int p = 0; p < 2; p++)
                ldsm_x4(b[2 * p][0], b[2 * p][1], b[2 * p + 1][0], b[2 * p + 1][1],
                        bAddr[p] + boff + s * 32);
#pragma unroll
            for (int mi = 0; mi < 4; mi++)
#pragma unroll
                for (int ni = 0; ni < 4; ni++)
                    mma16816(acc[mi][ni], a[mi], b[ni]);
        }
    }

    // epilogue: g_out += a_j * D ; Wn = bf16(D)
    float aj = g_a[jidx];
#pragma unroll
    for (int mi = 0; mi < 4; mi++) {
#pragma unroll
        for (int ni = 0; ni < 4; ni++) {
            int mA = m0 + wm * 64 + mi * 16 + (lane >> 2);
            int nA = n0 + wn * 32 + ni * 8 + (lane & 3) * 2;
#pragma unroll
            for (int hf = 0; hf < 2; hf++) {
                int m = mA + hf * 8;
                float v0 = acc[mi][ni][hf * 2 + 0];
                float v1 = acc[mi][ni][hf * 2 + 1];
                float* po = &g_out[(size_t)m * VN + nA];
                float2 o = *(float2*)po;
                o.x += aj * v0; o.y += aj * v1;
                *(float2*)po = o;
                *(__nv_bfloat162*)&Wn[(size_t)m * VN + nA] = __floats2bfloat162_rn(v0, v1);
            }
        }
    }
}

// ---------------- L2 normalize each chain row over V ----------------
__global__ void k_norm() {
    int n = blockIdx.x, tid = threadIdx.x;
    float* row = g_out + (size_t)n * VN;
    float loc[32];
    float ss = 0.f;
#pragma unroll
    for (int i = 0; i < 32; i++) {
        float v = row[i * 256 + tid];
        loc[i] = v;
        ss += v * v;
    }
    __shared__ float red[8];
    for (int o = 16; o; o >>= 1) ss += __shfl_xor_sync(0xffffffffu, ss, o);
    if ((tid & 31) == 0) red[tid >> 5] = ss;
    __syncthreads();
    if (tid == 0) {
        float t = 0.f;
        for (int i = 0; i < 8; i++) t += red[i];
        red[0] = t;
    }
    __syncthreads();
    float inv = 1.f / fmaxf(sqrtf(red[0]), 1e-12f);
#pragma unroll
    for (int i = 0; i < 32; i++) row[i * 256 + tid] = loc[i] * inv;
}

// ---------------- cl1 (16->32) + relu + maxpool8 -> xg ----------------
__global__ void k_cl1pool(const float* __restrict__ w, const float* __restrict__ bias) {
    int vg = blockIdx.x, b = blockIdx.y, c = threadIdx.x;
    float wr[16];
#pragma unroll
    for (int f = 0; f < 16; f++) wr[f] = w[c * 16 + f];
    float bb = bias[c];
    float m = 0.f;
    for (int vv = 0; vv < 8; vv++) {
        int v = vg * 8 + vv;
        float acc = bb;
#pragma unroll
        for (int f = 0; f < 16; f++)
            acc += wr[f] * g_out[(size_t)(b * F0N + f) * VN + v];
        m = fmaxf(m, acc);
    }
    g_xg[(size_t)b * 32768 + vg * 32 + c] = m;
}

__global__ void k_zero() {
    int i = blockIdx.x * 256 + threadIdx.x;
    if (i < 512 * 32) g_xhid_pre[i] = 0.f;
    if (i < 256 * 32) g_h1pre[i] = 0.f;
}

// ---------------- big MLP GEMMs (split-K, atomic accumulate) ----------------
// which==1: X = Xext (x_in, K=131072), acc = g_h1pre  (nn_fc1, F=256)
// which==0: X = g_xg (K=32768),        acc = g_xhid_pre (fc1, F=512)
// Weight loads vectorized to float4 (was the LSU-issue binder: 8 scalar LDG
// per 4 k-steps -> now 2 LDG.128).
__global__ void __launch_bounds__(256) k_mlpgemm(
    const float* __restrict__ Xext, int which,
    const float* __restrict__ W, int K) {
    __shared__ float xs[256 * 33];
    const float* __restrict__ X = which ? Xext : g_xg;
    float* __restrict__ acc = which ? g_h1pre : g_xhid_pre;
    int tid = threadIdx.x, lane = tid & 31, wrp = tid >> 5;
    int Kslice = K / gridDim.y;
    int kbase0 = blockIdx.y * Kslice;
    int f0 = blockIdx.x * 16 + wrp * 2;
    const float* w0p = W + (size_t)f0 * K;
    const float* w1p = W + (size_t)(f0 + 1) * K;
    float a0 = 0.f, a1 = 0.f;

    for (int kc = 0; kc < Kslice; kc += 256) {
        int kb = kbase0 + kc;
#pragma unroll
        for (int i = 0; i < 32; i++)
            xs[tid * 33 + i] = X[(size_t)i * K + kb + tid];
        __syncthreads();
#pragma unroll 4
        for (int kk = 0; kk < 256; kk += 4) {
            float4 w0 = *(const float4*)(w0p + kb + kk);
            float4 w1 = *(const float4*)(w1p + kb + kk);
            float x0 = xs[(kk + 0) * 33 + lane];
            float x1 = xs[(kk + 1) * 33 + lane];
            float x2 = xs[(kk + 2) * 33 + lane];
            float x3 = xs[(kk + 3) * 33 + lane];
            a0 += w0.x * x0 + w0.y * x1 + w0.z * x2 + w0.w * x3;
            a1 += w1.x * x0 + w1.y * x1 + w1.z * x2 + w1.w * x3;
        }
        __syncthreads();
    }
    atomicAdd(&acc[f0 * 32 + lane], a0);
    atomicAdd(&acc[(f0 + 1) * 32 + lane], a1);
}

// ---------------- bias+relu+BN (train stats) for h1 ----------------
__global__ void k_bn1(const float* __restrict__ bias, const float* __restrict__ gamma,
                      const float* __restrict__ beta) {
    int f = blockIdx.x, b = threadIdx.x;
    float v = fmaxf(g_h1pre[f * 32 + b] + bias[f], 0.f);
    float s = v, s2 = v * v;
    for (int o = 16; o; o >>= 1) {
        s  += __shfl_xor_sync(0xffffffffu, s, o);
        s2 += __shfl_xor_sync(0xffffffffu, s2, o);
    }
    float mean = s / 32.f, var = s2 / 32.f - mean * mean;
    g_h1n[f * 32 + b] = (v - mean) * rsqrtf(var + 1e-5f) * gamma[f] + beta[f];
}

// ---------------- fc2 + relu + BN2 ----------------
__global__ void k_fc2bn2(const float* __restrict__ w, const float* __restrict__ bias,
                         const float* __restrict__ gamma, const float* __restrict__ beta) {
    int o = blockIdx.x, b = threadIdx.x;
    float acc = bias[o];
    for (int k = 0; k < 256; k++)
        acc += w[o * 256 + k] * g_h1n[k * 32 + b];
    float v = fmaxf(acc, 0.f);
    float s = v, s2 = v * v;
    for (int sh = 16; sh; sh >>= 1) {
        s  += __shfl_xor_sync(0xffffffffu, s, sh);
        s2 += __shfl_xor_sync(0xffffffffu, s2, sh);
    }
    float mean = s / 32.f, var = s2 / 32.f - mean * mean;
    g_h2n[o * 32 + b] = (v - mean) * rsqrtf(var + 1e-5f) * gamma[o] + beta[o];
}

// ---------------- fusion head ----------------
__global__ void k_head(const float* __restrict__ fc1b, const float* __restrict__ sw,
                       const float* __restrict__ sb, float* __restrict__ out) {
    int tid = threadIdx.x;
    if (tid >= 320) return;
    int o = tid >> 5, b = tid & 31;
    float acc = sb[o];
    for (int f = 0; f < 512; f++)
        acc += sw[o * 640 + f] * fmaxf(g_xhid_pre[f * 32 + b] + fc1b[f], 0.f);
    for (int f = 0; f < 128; f++)
        acc += sw[o * 640 + 512 + f] * g_h2n[f * 32 + b];
    out[b * 10 + o] = acc;
}

// ---------------- launch ----------------
extern "C" void kernel_launch(void* const* d_in, const int* in_sizes, int n_in,
                              void* d_out, int out_size) {
    const float* x_in     = (const float*)d_in[0];
    const float* L        = (const float*)d_in[1];
    const float* theta    = (const float*)d_in[2];
    const float* cl1_w    = (const float*)d_in[3];
    const float* cl1_b    = (const float*)d_in[4];
    const float* fc1_w    = (const float*)d_in[5];
    const float* fc1_b    = (const float*)d_in[6];
    const float* nn1_w    = (const float*)d_in[7];
    const float* nn1_b    = (const float*)d_in[8];
    const float* bn1_g    = (const float*)d_in[9];
    const float* bn1_b    = (const float*)d_in[10];
    const float* nn2_w    = (const float*)d_in[11];
    const float* nn2_b    = (const float*)d_in[12];
    const float* bn2_g    = (const float*)d_in[13];
    const float* bn2_b    = (const float*)d_in[14];
    const float* sum2_w   = (const float*)d_in[15];
    const float* sum2_b   = (const float*)d_in[16];
    float* out = (float*)d_out;

    static int smem_set = 0;
    if (!smem_set) {
        cudaFuncSetAttribute(k_gemm, cudaFuncAttributeMaxDynamicSharedMemorySize, GEMM_SMEM);
        smem_set = 1;
    }

    k_bern<<<1, 32>>>(theta);
    k_cvtL<<<65536, 256>>>(L);
    k_init<<<dim3(128, 32), 256>>>(x_in);

    for (int j = 1; j <= KDEG; j++)
        k_gemm<<<dim3(4, 64), 256, GEMM_SMEM>>>((j & 1) ? 1 : 0, j);

    k_norm<<<512, 256>>>();
    k_cl1pool<<<dim3(1024, 32), 32>>>(cl1_w, cl1_b);
    k_zero<<<96, 256>>>();
    k_mlpgemm<<<dim3(16, 16), 256>>>(x_in, 1, nn1_w, 131072);
    k_mlpgemm<<<dim3(32, 8), 256>>>(nullptr, 0, fc1_w, 32768);
    k_bn1<<<256, 32>>>(nn1_b, bn1_g, bn1_b);
    k_fc2bn2<<<128, 32>>>(nn2_w, nn2_b, bn2_g, bn2_b);
    k_head<<<1, 320>>>(fc1_b, sum2_w, sum2_b, out);
}